// round 17
// baseline (speedup 1.0000x reference)
#include <cuda_runtime.h>
#include <cuda_bf16.h>
#include <math.h>
#include <stdint.h>

#define SQ 68            // padded smem stride for staging rows
#define HH 0.025f        // 0.5*STEP
#define HS 0.05f         // STEP

__device__ float g_Mm[4096];      // M = Wdec Wdec^T
__device__ float g_Vm[4096];      // eigenvectors, V[i*64+e]
__device__ float g_LAM[64];       // eigenvalues
__device__ float g_MU[8192];      // x @ Wenc (original basis, for c_b)
__device__ float g_Y [8192];      // x @ Wdec^T
__device__ float g_MUZ[8192];     // mu @ V
__device__ float g_VZ [8192];     // (y - mu) @ V
__device__ float g_BETA[18];
__device__ float g_DBETA[17];
__device__ unsigned g_KEYS[34];
__device__ float g_SLW[131072];   // [b][n]

// ---------------- packed f32x2 helpers --------------------------------------
typedef unsigned long long f2_t;

__device__ __forceinline__ f2_t f2fma(f2_t a, f2_t b, f2_t c) {
    f2_t d; asm("fma.rn.f32x2 %0,%1,%2,%3;" : "=l"(d) : "l"(a), "l"(b), "l"(c));
    return d;
}
__device__ __forceinline__ f2_t f2add(f2_t a, f2_t b) {
    f2_t d; asm("add.rn.f32x2 %0,%1,%2;" : "=l"(d) : "l"(a), "l"(b));
    return d;
}
__device__ __forceinline__ f2_t f2mul(f2_t a, f2_t b) {
    f2_t d; asm("mul.rn.f32x2 %0,%1,%2;" : "=l"(d) : "l"(a), "l"(b));
    return d;
}
__device__ __forceinline__ f2_t f2pack(float lo, float hi) {
    f2_t d; asm("mov.b64 %0,{%1,%2};" : "=l"(d)
                : "r"(__float_as_uint(lo)), "r"(__float_as_uint(hi)));
    return d;
}
__device__ __forceinline__ f2_t f2splat(float x) { return f2pack(x, x); }
__device__ __forceinline__ void f2unpack(f2_t a, float& lo, float& hi) {
    unsigned l, h; asm("mov.b64 {%0,%1},%2;" : "=r"(l), "=r"(h) : "l"(a));
    lo = __uint_as_float(l); hi = __uint_as_float(h);
}

// ---------------- threefry2x32-20 (JAX partitionable) -----------------------
__device__ __forceinline__ uint2 tf2x32(unsigned k0, unsigned k1,
                                        unsigned c0, unsigned c1) {
    unsigned ks2 = k0 ^ k1 ^ 0x1BD11BDAu;
    unsigned x0 = c0 + k0, x1 = c1 + k1;
#define TFR(r) { x0 += x1; x1 = (x1<<(r))|(x1>>(32-(r))); x1 ^= x0; }
    TFR(13) TFR(15) TFR(26) TFR(6)  x0 += k1;  x1 += ks2 + 1u;
    TFR(17) TFR(29) TFR(16) TFR(24) x0 += ks2; x1 += k0 + 2u;
    TFR(13) TFR(15) TFR(26) TFR(6)  x0 += k0;  x1 += k1 + 3u;
    TFR(17) TFR(29) TFR(16) TFR(24) x0 += k1;  x1 += ks2 + 4u;
    TFR(13) TFR(15) TFR(26) TFR(6)  x0 += ks2; x1 += k0 + 5u;
#undef TFR
    return make_uint2(x0, x1);
}
__device__ __forceinline__ unsigned tf_bits(unsigned k0, unsigned k1, unsigned i) {
    uint2 h = tf2x32(k0, k1, 0u, i);
    return h.x ^ h.y;
}

__device__ __forceinline__ float bits2normal(unsigned bits) {
    const float LO = -0x1.fffffep-1f;
    float f = __uint_as_float((bits >> 9) | 0x3F800000u) - 1.0f;
    float u = fmaxf(LO, f * 2.0f + LO);
    float w = -log1pf(-u * u), p;
    if (w < 5.0f) {
        w -= 2.5f;
        p = 2.81022636e-08f;
        p = fmaf(p, w, 3.43273939e-07f);  p = fmaf(p, w, -3.5233877e-06f);
        p = fmaf(p, w, -4.39150654e-06f); p = fmaf(p, w, 0.00021858087f);
        p = fmaf(p, w, -0.00125372503f);  p = fmaf(p, w, -0.00417768164f);
        p = fmaf(p, w, 0.246640727f);     p = fmaf(p, w, 1.50140941f);
    } else {
        w = sqrtf(w) - 3.0f;
        p = -0.000200214257f;
        p = fmaf(p, w, 0.000100950558f);  p = fmaf(p, w, 0.00134934322f);
        p = fmaf(p, w, -0.00367342844f);  p = fmaf(p, w, 0.00573950773f);
        p = fmaf(p, w, -0.0076224613f);   p = fmaf(p, w, 0.00943887047f);
        p = fmaf(p, w, 1.00167406f);      p = fmaf(p, w, 2.83297682f);
    }
    return 1.41421356237f * (p * u);
}

// ---------------- prep: M, mu, y, betas, keys -------------------------------
__global__ void prep_k(const float* __restrict__ x,
                       const float* __restrict__ Wenc,
                       const float* __restrict__ Wdec) {
    int idx = blockIdx.x * 256 + threadIdx.x;
    if (idx < 4096) {
        int i = idx >> 6, j = idx & 63;
        float s = 0.f;
        #pragma unroll 8
        for (int c = 0; c < 64; ++c) s = fmaf(Wdec[i*64+c], Wdec[j*64+c], s);
        g_Mm[idx] = s;
    } else if (idx < 12288) {
        int e = idx - 4096, b = e >> 6, d = e & 63;
        float smu = 0.f, sy = 0.f;
        #pragma unroll 8
        for (int c = 0; c < 64; ++c) {
            float xv = x[b*64+c];
            smu = fmaf(xv, Wenc[c*64+d], smu);
            sy  = fmaf(xv, Wdec[d*64+c], sy);
        }
        g_MU[e] = smu; g_Y[e] = sy;
    } else if (idx == 12288) {
        double bb[18];
        for (int i = 0; i < 18; ++i) {
            double z = 4.0 * (2.0 * ((double)i / 17.0) - 1.0);
            bb[i] = 1.0 / (1.0 + exp(-z));
        }
        double b0 = bb[0], sc = bb[17] - bb[0];
        for (int i = 0; i < 18; ++i) g_BETA[i] = (float)((bb[i]-b0)/sc);
        for (int i = 0; i < 17; ++i)
            g_DBETA[i] = (float)(((bb[i+1]-b0)/sc) - ((bb[i]-b0)/sc));
        for (int k = 1; k <= 16; ++k) {
            uint2 r = tf2x32(0u, 42u, 0u, (unsigned)k);  // fold_in(key(42), k)
            g_KEYS[2*k] = r.x; g_KEYS[2*k+1] = r.y;
        }
    }
}

// ---------------- one-block parallel cyclic Jacobi --------------------------
__global__ void jacobi_k() {
    __shared__ float A[4096], Vv[4096];
    __shared__ float cs[32], sn[32];
    __shared__ int pp[32], qq[32];
    const int tid = threadIdx.x;  // 256
    for (int i = tid; i < 4096; i += 256) {
        A[i]  = g_Mm[i];
        Vv[i] = ((i >> 6) == (i & 63)) ? 1.f : 0.f;
    }
    __syncthreads();
    for (int sweep = 0; sweep < 10; ++sweep)
    for (int r = 0; r < 63; ++r) {
        if (tid < 32) {
            int p_, q_;
            if (tid == 0) { p_ = 63; q_ = r; }
            else { p_ = (r + tid) % 63; q_ = (r - tid + 63) % 63; }
            if (p_ > q_) { int t = p_; p_ = q_; q_ = t; }
            float apq = A[p_*64 + q_];
            float c = 1.f, s = 0.f;
            if (fabsf(apq) > 1e-12f) {
                float app = A[p_*64+p_], aqq = A[q_*64+q_];
                float th = 0.5f * (aqq - app) / apq;
                float t  = copysignf(1.f, th) / (fabsf(th) + sqrtf(1.f + th*th));
                c = rsqrtf(1.f + t*t);
                s = t * c;
            }
            cs[tid] = c; sn[tid] = s; pp[tid] = p_; qq[tid] = q_;
        }
        __syncthreads();
        // row update: A <- J^T A
        for (int j = tid; j < 2048; j += 256) {
            int pr = j >> 6, col = j & 63;
            int P = pp[pr], Q = qq[pr];
            float c = cs[pr], s = sn[pr];
            float ap = A[P*64 + col], aq = A[Q*64 + col];
            A[P*64 + col] = c*ap - s*aq;
            A[Q*64 + col] = s*ap + c*aq;
        }
        __syncthreads();
        // col update: A <- A J ; V <- V J
        for (int j = tid; j < 2048; j += 256) {
            int pr = j >> 6, row = j & 63;
            int P = pp[pr], Q = qq[pr];
            float c = cs[pr], s = sn[pr];
            float ap = A[row*64 + P], aq = A[row*64 + Q];
            A[row*64 + P] = c*ap - s*aq;
            A[row*64 + Q] = s*ap + c*aq;
            float vp = Vv[row*64 + P], vq = Vv[row*64 + Q];
            Vv[row*64 + P] = c*vp - s*vq;
            Vv[row*64 + Q] = s*vp + c*vq;
        }
        __syncthreads();
    }
    for (int i = tid; i < 4096; i += 256) g_Vm[i] = Vv[i];
    if (tid < 64) g_LAM[tid] = A[tid*64 + tid];
}

// ---------------- rotate per-b vectors into eigenbasis ----------------------
__global__ void prep2_k() {
    int idx = blockIdx.x * 256 + threadIdx.x;   // 8192
    int b = idx >> 6, e = idx & 63;
    float sm = 0.f, sv = 0.f;
    #pragma unroll 8
    for (int i = 0; i < 64; ++i) {
        float vi = g_Vm[i*64 + e];
        float m  = g_MU[b*64 + i];
        sm = fmaf(m, vi, sm);
        sv = fmaf(g_Y[b*64 + i] - m, vi, sv);
    }
    g_MUZ[idx] = sm; g_VZ[idx] = sv;
}

// ---------------- main: 64 chains/block, eigenbasis dynamics ----------------
__global__ void __launch_bounds__(128)
ais_main(const float* __restrict__ qn) {
    __shared__ float sV[4096];
    __shared__ float sE[64 * SQ];
    const int tid = threadIdx.x;
    const int jg = tid & 7, cq = tid >> 3;        // cq 0..15
    const int b = blockIdx.x, n0 = blockIdx.y * 32;
    const int j0 = jg * 8;

    for (int i = tid; i < 4096; i += 128) sV[i] = g_Vm[i];

    f2_t muz2[4], vz2[4], lam2[4], nhlam2[4];
    {
        float4 a = *(const float4*)&g_MUZ[b*64 + j0];
        float4 c = *(const float4*)&g_MUZ[b*64 + j0 + 4];
        muz2[0]=f2pack(a.x,a.y); muz2[1]=f2pack(a.z,a.w);
        muz2[2]=f2pack(c.x,c.y); muz2[3]=f2pack(c.z,c.w);
        float4 d = *(const float4*)&g_VZ[b*64 + j0];
        float4 e = *(const float4*)&g_VZ[b*64 + j0 + 4];
        vz2[0]=f2pack(d.x,d.y); vz2[1]=f2pack(d.z,d.w);
        vz2[2]=f2pack(e.x,e.y); vz2[3]=f2pack(e.z,e.w);
        float4 l0 = *(const float4*)&g_LAM[j0];
        float4 l1 = *(const float4*)&g_LAM[j0 + 4];
        lam2[0]=f2pack(l0.x,l0.y); lam2[1]=f2pack(l0.z,l0.w);
        lam2[2]=f2pack(l1.x,l1.y); lam2[3]=f2pack(l1.z,l1.w);
        f2_t nh = f2splat(-0.5f);
        #pragma unroll
        for (int h = 0; h < 4; ++h) nhlam2[h] = f2mul(nh, lam2[h]);
    }

    int nn[4]; unsigned nb[4];
    #pragma unroll
    for (int m = 0; m < 4; ++m) {
        nn[m] = n0 + 2*cq + (m >> 1) + (m & 1)*512;
        nb[m] = (unsigned)nn[m]*8192u + (unsigned)b*64u + (unsigned)j0;
    }

    f2_t z2[4][4], p2[4][4];
    float slw[4] = {0.f, 0.f, 0.f, 0.f};
    const f2_t hs2 = f2splat(HS), hh2 = f2splat(HH);

#define ROTVEC(DST) do {                                                     \
    _Pragma("unroll") for (int m = 0; m < 4; ++m)                            \
    _Pragma("unroll") for (int h = 0; h < 4; ++h) DST[m][h] = 0ull;          \
    _Pragma("unroll 4") for (int i = 0; i < 64; ++i) {                       \
        float4 ev = *(const float4*)&sE[i*SQ + cq*4];                        \
        ulonglong2 va = *(const ulonglong2*)&sV[i*64 + j0];                  \
        ulonglong2 vb = *(const ulonglong2*)&sV[i*64 + j0 + 4];              \
        f2_t vv[4] = {va.x, va.y, vb.x, vb.y};                               \
        f2_t es[4] = {f2splat(ev.x), f2splat(ev.y),                          \
                      f2splat(ev.z), f2splat(ev.w)};                         \
        _Pragma("unroll") for (int m = 0; m < 4; ++m)                        \
        _Pragma("unroll") for (int h = 0; h < 4; ++h)                        \
            DST[m][h] = f2fma(es[m], vv[h], DST[m][h]);                      \
    } } while (0)

#define ADDW(DB) do {                                                        \
    _Pragma("unroll") for (int m = 0; m < 4; ++m) {                          \
        f2_t wc2 = 0ull;                                                     \
        _Pragma("unroll") for (int h = 0; h < 4; ++h) {                      \
            f2_t u = f2fma(nhlam2[h], z2[m][h], vz2[h]);                     \
            wc2 = f2fma(z2[m][h], u, wc2);                                   \
        }                                                                    \
        float wl, wh2; f2unpack(wc2, wl, wh2);                               \
        float wv = wl + wh2;                                                 \
        _Pragma("unroll") for (int off = 1; off < 8; off <<= 1)              \
            wv += __shfl_xor_sync(0xffffffffu, wv, off);                     \
        slw[m] = fmaf((DB), wv, slw[m]);                                     \
    } } while (0)

    // ---- init: stage raw q_noise, rotate, add muz; w at k=0 ----
    {
        float buf[4][8];
        #pragma unroll
        for (int m = 0; m < 4; ++m) {
            const float* src = qn + (size_t)nn[m]*8192 + b*64 + j0;
            float4 a = *(const float4*)src, c = *(const float4*)(src + 4);
            buf[m][0]=a.x; buf[m][1]=a.y; buf[m][2]=a.z; buf[m][3]=a.w;
            buf[m][4]=c.x; buf[m][5]=c.y; buf[m][6]=c.z; buf[m][7]=c.w;
        }
        #pragma unroll
        for (int e = 0; e < 8; ++e)
            *(float4*)&sE[(j0+e)*SQ + cq*4] =
                make_float4(buf[0][e], buf[1][e], buf[2][e], buf[3][e]);
    }
    __syncthreads();
    ROTVEC(z2);
    #pragma unroll
    for (int m = 0; m < 4; ++m)
    #pragma unroll
    for (int h = 0; h < 4; ++h) z2[m][h] = f2add(z2[m][h], muz2[h]);
    ADDW(g_DBETA[0]);

    #pragma unroll 1
    for (int k = 1; k <= 16; ++k) {
        const float bk = g_BETA[k], db = g_DBETA[k];
        const unsigned K0 = g_KEYS[2*k], K1 = g_KEYS[2*k+1];

        f2_t chk2[4], pa2[4];
        {
            f2_t nhbk = f2splat(-HH * bk), nhh = f2splat(-HH), bk2 = f2splat(bk);
            #pragma unroll
            for (int h = 0; h < 4; ++h) {
                chk2[h] = f2add(f2mul(nhbk, lam2[h]), nhh);
                pa2[h]  = f2mul(hh2, f2fma(bk2, vz2[h], muz2[h]));
            }
        }

        // momentum resample: generate eps in original basis, stage to smem
        __syncthreads();
        #pragma unroll 2
        for (int e = 0; e < 8; ++e) {
            float4 v;
            v.x = bits2normal(tf_bits(K0, K1, nb[0] + e));
            v.y = bits2normal(tf_bits(K0, K1, nb[1] + e));
            v.z = bits2normal(tf_bits(K0, K1, nb[2] + e));
            v.w = bits2normal(tf_bits(K0, K1, nb[3] + e));
            *(float4*)&sE[(j0+e)*SQ + cq*4] = v;
        }
        __syncthreads();
        ROTVEC(p2);   // pz = eps @ V

        // 3 leapfrog steps, fully diagonal in eigenbasis
        #pragma unroll
        for (int leap = 0; leap < 3; ++leap) {
            #pragma unroll
            for (int m = 0; m < 4; ++m)
            #pragma unroll
            for (int h = 0; h < 4; ++h) {
                f2_t pv = f2add(p2[m][h], pa2[h]);
                pv = f2fma(chk2[h], z2[m][h], pv);          // half kick
                f2_t zv = f2fma(hs2, pv, z2[m][h]);          // drift
                pv = f2add(pv, pa2[h]);
                pv = f2fma(chk2[h], zv, pv);                 // half kick
                p2[m][h] = pv; z2[m][h] = zv;
            }
        }
        ADDW(db);
    }

    if (jg == 0) {
        #pragma unroll
        for (int m = 0; m < 4; ++m) g_SLW[b*1024 + nn[m]] = slw[m];
    }
}

// ---------------- logsumexp over n, + c_b -----------------------------------
__global__ void lse_k(const float* __restrict__ x, float* __restrict__ out) {
    __shared__ float red[256];
    const int b = blockIdx.x, tid = threadIdx.x;
    float part = 0.f;
    for (int d = tid; d < 64; d += 256) {
        float xv = x[b*64+d], mv = g_MU[b*64+d];
        part += 0.5f * (mv*mv - xv*xv);
    }
    red[tid] = part; __syncthreads();
    for (int s = 128; s > 0; s >>= 1) { if (tid < s) red[tid] += red[tid+s]; __syncthreads(); }
    float cb = red[0] - 32.0f * 1.8378770664093453f;
    __syncthreads();
    float mx = -1e30f;
    for (int i = tid; i < 1024; i += 256) mx = fmaxf(mx, g_SLW[b*1024+i]);
    red[tid] = mx; __syncthreads();
    for (int s = 128; s > 0; s >>= 1) { if (tid < s) red[tid] = fmaxf(red[tid], red[tid+s]); __syncthreads(); }
    mx = red[0]; __syncthreads();
    float sum = 0.f;
    for (int i = tid; i < 1024; i += 256) sum += expf(g_SLW[b*1024+i] - mx);
    red[tid] = sum; __syncthreads();
    for (int s = 128; s > 0; s >>= 1) { if (tid < s) red[tid] += red[tid+s]; __syncthreads(); }
    if (tid == 0) out[b] = cb + mx + logf(red[0]) - 6.931471805599453f; // log 1024
}

extern "C" void kernel_launch(void* const* d_in, const int* in_sizes, int n_in,
                              void* d_out, int out_size) {
    const float* x    = (const float*)d_in[0];
    const float* Wenc = (const float*)d_in[1];
    const float* Wdec = (const float*)d_in[2];
    const float* qn   = (const float*)d_in[3];
    float* out = (float*)d_out;
    (void)in_sizes; (void)n_in; (void)out_size;

    prep_k<<<49, 256>>>(x, Wenc, Wdec);
    jacobi_k<<<1, 256>>>();
    prep2_k<<<32, 256>>>();
    ais_main<<<dim3(128, 16), 128>>>(qn);
    lse_k<<<128, 256>>>(x, out);
}